// round 9
// baseline (speedup 1.0000x reference)
#include <cuda_runtime.h>
#include <math.h>

#define NB   2
#define NHD  8
#define HD   32
#define CH   256
#define HI   40
#define WIM  40
#define HW   1600
#define WSZ  15
#define WS2  225
#define NEGV 1e8f
#define INV_T 0.17677669529663687f   // 1/sqrt(32)

#define OUT_ELEMS  (HW*NB*CH)            // 819200
#define ATTN_ELEMS (NB*NHD*HW*WS2)       // 5760000

// ---- scratch ----
__device__ float g_qp[NB*NHD*HW*HD];     // [n][h][q][d] unscaled
__device__ float g_kp[NB*NHD*HW*HD];     // [n][h][j][d] scaled by 1/T
__device__ float g_vp[NB*NHD*HW*HD];
__device__ float g_ctx[HW*NB*CH];        // [i][n][c]
__device__ float g_rel[NB*NHD*WS2*HW];   // [n][h][w][q]  rel logits
__device__ float g_pb[ATTN_ELEMS];       // fallback p storage

// ============================================================
// Kernel 1: fused QKV projection (unchanged).
// ============================================================
__global__ void __launch_bounds__(256, 2) proj_kernel(
    const float* __restrict__ q, const float* __restrict__ k, const float* __restrict__ v,
    const float* __restrict__ Wq, const float* __restrict__ bq,
    const float* __restrict__ Wk, const float* __restrict__ bk,
    const float* __restrict__ Wv, const float* __restrict__ bv)
{
    __shared__ __align__(16) float Ws[128 * 33];
    __shared__ __align__(16) float Bs[32][64];

    int z = blockIdx.z;
    int n = z & 1, t = z >> 1;
    const float* X; const float* W; const float* b; float* Y; float scale;
    if (t == 0)      { X = q; W = Wq; b = bq; Y = g_qp; scale = 1.0f;  }
    else if (t == 1) { X = k; W = Wk; b = bk; Y = g_kp; scale = INV_T; }
    else             { X = v; W = Wv; b = bv; Y = g_vp; scale = 1.0f;  }
    X += (size_t)n * CH * HW;

    int o0 = blockIdx.y * 128, p0 = blockIdx.x * 64;
    int tid = threadIdx.x;
    int tx = tid & 15, ty = tid >> 4;

    float acc[8][4] = {};

    for (int k0 = 0; k0 < CH; k0 += 32) {
#pragma unroll
        for (int s = 0; s < 16; s++) {
            int idx = tid + s * 256;
            int row = idx >> 5, col = idx & 31;
            Ws[row * 33 + col] = W[(size_t)(o0 + row) * CH + k0 + col];
        }
#pragma unroll
        for (int s = 0; s < 8; s++) {
            int idx = tid + s * 256;
            int col = idx & 63, row = idx >> 6;
            Bs[row][col] = X[(size_t)(k0 + row) * HW + p0 + col];
        }
        __syncthreads();
#pragma unroll
        for (int cc = 0; cc < 32; cc++) {
            float4 b4 = *reinterpret_cast<const float4*>(&Bs[cc][tx * 4]);
            float bb[4] = {b4.x, b4.y, b4.z, b4.w};
            float aa[8];
#pragma unroll
            for (int i = 0; i < 8; i++) aa[i] = Ws[(ty * 8 + i) * 33 + cc];
#pragma unroll
            for (int i = 0; i < 8; i++)
#pragma unroll
                for (int j = 0; j < 4; j++)
                    acc[i][j] = fmaf(aa[i], bb[j], acc[i][j]);
        }
        __syncthreads();
    }

#pragma unroll
    for (int i = 0; i < 8; i++) {
        int o = o0 + ty * 8 + i;
        int h = o >> 5, d = o & 31;
        float bias = b[o];
#pragma unroll
        for (int j = 0; j < 4; j++) {
            int p = p0 + tx * 4 + j;
            float val = (acc[i][j] + bias) * scale;
            Y[((size_t)(n * NHD + h) * HW + p) * HD + d] = val;
        }
    }
}

// ============================================================
// Kernel 2: rel logits GEMM. rel[n,h,w,q] = q_unscaled . relw[h,w] + relb.
// grid (25 qtiles, NHD, NB), 256 thr. Thread = (qi 0..63, wg 0..3).
// ============================================================
__global__ void __launch_bounds__(256) relgemm_kernel(
    const float* __restrict__ relw_g,   // [NHD][WS2][HD]
    const float* __restrict__ relb_g)   // [NHD][WS2]
{
    __shared__ __align__(16) float sW[WS2 * HD];   // [w][d]
    __shared__ float sb[WS2];

    int q0 = blockIdx.x * 64, h = blockIdx.y, n = blockIdx.z;
    int tid = threadIdx.x;
    int nh = n * NHD + h;

    {
        const float4* src = reinterpret_cast<const float4*>(relw_g + (size_t)h * WS2 * HD);
        float4* dst = reinterpret_cast<float4*>(sW);
        for (int i = tid; i < WS2 * HD / 4; i += 256) dst[i] = src[i];
        const float* bs = relb_g + (size_t)h * WS2;
        for (int i = tid; i < WS2; i += 256) sb[i] = bs[i];
    }
    __syncthreads();

    int qi = tid & 63, wg = tid >> 6;
    int qq = q0 + qi;
    float4 qv[8];
    {
        const float4* qsrc = reinterpret_cast<const float4*>(
            g_qp + (size_t)(nh * HW + qq) * HD);
#pragma unroll
        for (int u = 0; u < 8; u++) qv[u] = qsrc[u];
    }
    float* dst = g_rel + (size_t)nh * WS2 * HW + qq;
#pragma unroll 1
    for (int w = wg; w < WS2; w += 4) {
        const float4* r4 = reinterpret_cast<const float4*>(sW + w * HD);
        float4 a = make_float4(0.f, 0.f, 0.f, 0.f);
#pragma unroll
        for (int u = 0; u < 8; u++) {
            float4 rv = r4[u], qu = qv[u];
            a.x = fmaf(qu.x, rv.x, a.x);
            a.y = fmaf(qu.y, rv.y, a.y);
            a.z = fmaf(qu.z, rv.z, a.z);
            a.w = fmaf(qu.w, rv.w, a.w);
        }
        dst[(size_t)w * HW] = (a.x + a.y) + (a.z + a.w) + sb[w];
    }
}

// ============================================================
// Kernel 3: attention core. Block per (qy, h, n). 320 threads, 2 CTAs/SM.
// K/V read directly from global (L1-cached). smem = logits/p only.
// ============================================================
#define LP 228

__global__ void __launch_bounds__(320, 2) attn_kernel(float* __restrict__ p_out)
{
    __shared__ __align__(16) float sL[WIM * LP];

    int qy = blockIdx.x, h = blockIdx.y, n = blockIdx.z;
    int tid = threadIdx.x;
    int nh = n * NHD + h;
    int nh_base = nh * HW;

    // ---- logits: thread = (qx = tid%40, wg = tid/40 in 0..7) ----
    {
        int qx = tid % 40;
        int wg = tid / 40;
        float4 qv[8];
        {
            const float4* qsrc = reinterpret_cast<const float4*>(
                g_qp + (size_t)(nh_base + qy * WIM + qx) * HD);
#pragma unroll
            for (int u = 0; u < 8; u++) qv[u] = qsrc[u];
        }
        const float* relp = g_rel + (size_t)nh * WS2 * HW + qy * WIM + qx;
        int wy = 0, wx = wg;
#pragma unroll 1
        for (int w = wg; w < WS2; w += 8) {
            int ky = qy + wy - 7, kx = qx + wx - 7;
            bool img = ((unsigned)ky < HI) & ((unsigned)kx < WIM);
            int kyc = min(max(ky, 0), HI - 1);
            int kxc = min(max(kx, 0), WIM - 1);
            const float4* k4 = reinterpret_cast<const float4*>(
                g_kp + (size_t)(nh_base + kyc * WIM + kxc) * HD);
            float4 a = make_float4(0.f, 0.f, 0.f, 0.f);
#pragma unroll
            for (int u = 0; u < 8; u++) {
                float4 kv = k4[u], qu = qv[u];
                a.x = fmaf(qu.x, kv.x, a.x);
                a.y = fmaf(qu.y, kv.y, a.y);
                a.z = fmaf(qu.z, kv.z, a.z);
                a.w = fmaf(qu.w, kv.w, a.w);
            }
            float qk = (a.x + a.y) + (a.z + a.w);
            float rel = __ldg(relp + (size_t)w * HW);
            sL[qx * LP + w] = (img ? qk : -NEGV) + rel;
            wx += 8;
            if (wx >= WSZ) { wx -= WSZ; wy++; }
        }
    }
    __syncthreads();

    // ---- softmax: 10 warps x 4 queries; write p to sL and p_out ----
    {
        int warp = tid >> 5, lane = tid & 31;
#pragma unroll 1
        for (int qq = 0; qq < 4; qq++) {
            int qx = warp * 4 + qq;
            float* Lp = sL + qx * LP;
            float vals[8];
            float m = -3.0e38f;
#pragma unroll
            for (int u = 0; u < 8; u++) {
                int w = lane + u * 32;
                vals[u] = (w < WS2) ? Lp[w] : -3.0e38f;
                m = fmaxf(m, vals[u]);
            }
#pragma unroll
            for (int off = 16; off > 0; off >>= 1)
                m = fmaxf(m, __shfl_xor_sync(0xffffffffu, m, off));
            float s = 0.0f;
#pragma unroll
            for (int u = 0; u < 8; u++) { float p = __expf(vals[u] - m); vals[u] = p; s += p; }
#pragma unroll
            for (int off = 16; off > 0; off >>= 1)
                s += __shfl_xor_sync(0xffffffffu, s, off);
            float inv = 1.0f / s;
            float* gp = p_out + (size_t)(nh_base + qy * WIM + qx) * WS2;
#pragma unroll
            for (int u = 0; u < 8; u++) {
                int w = lane + u * 32;
                if (w < WS2) {
                    float p = vals[u] * inv;
                    Lp[w] = p;
                    gp[w] = p;
                }
            }
        }
    }
    __syncthreads();

    // ---- V aggregation: thread = (qx = tid>>3, dg = tid&7), float4 over d ----
    {
        int qx = tid >> 3, dg = tid & 7;
        const float* vbase = g_vp + (size_t)nh_base * HD + dg * 4;
        const float* Lp = sL + qx * LP;
        float4 acc = make_float4(0.f, 0.f, 0.f, 0.f);
#pragma unroll 1
        for (int wy = 0; wy < WSZ; wy++) {
            int kyc = min(max(qy + wy - 7, 0), HI - 1);
            const float* rowp = vbase + (size_t)kyc * WIM * HD;
            const float* Lrow = Lp + wy * WSZ;
#pragma unroll
            for (int wx = 0; wx < WSZ; wx++) {
                int kxc = min(max(qx + wx - 7, 0), WIM - 1);
                float p = Lrow[wx];                 // p==0 kills clamped/OOB taps
                float4 v = *reinterpret_cast<const float4*>(rowp + kxc * HD);
                acc.x = fmaf(p, v.x, acc.x);
                acc.y = fmaf(p, v.y, acc.y);
                acc.z = fmaf(p, v.z, acc.z);
                acc.w = fmaf(p, v.w, acc.w);
            }
        }
        int iy = qy * WIM + qx;
        *reinterpret_cast<float4*>(
            g_ctx + ((size_t)iy * NB + n) * CH + h * HD + dg * 4) = acc;
    }
}

// ============================================================
// Kernel 4: agg_bias GEMM: ctx[q,n, h*32+d] += sum_w p[n,h,q,w] * relv[h,d,w]
// grid (25 qtiles, NHD, NB), 512 thr. smem: p tile + relv (w-major).
// ============================================================
#define AB_SP      0                    // 64*228 = 14592
#define AB_SV      14592                // 225*32 = 7200
#define AB_FLOATS  21792
#define AB_BYTES   (AB_FLOATS * 4)      // 87168

__global__ void __launch_bounds__(512) abgemm_kernel(
    const float* __restrict__ relv_g,   // [NHD][HD][WS2]
    const float* __restrict__ p_src)    // [n,h,q,w]
{
    extern __shared__ __align__(16) float sm[];
    float* sP = sm + AB_SP;
    float* sV = sm + AB_SV;

    int q0 = blockIdx.x * 64, h = blockIdx.y, n = blockIdx.z;
    int tid = threadIdx.x;
    int nh = n * NHD + h;

    {
        const float* src = p_src + ((size_t)nh * HW + q0) * WS2;
        for (int i = tid; i < 64 * WS2; i += 512) {
            int r = i / WS2, w = i - r * WS2;
            sP[r * LP + w] = src[i];
        }
        const float* rv = relv_g + (size_t)h * HD * WS2;
        for (int i = tid; i < HD * WS2; i += 512) {
            int d = i / WS2, w = i - d * WS2;
            sV[w * HD + d] = rv[i];
        }
    }
    __syncthreads();

    int qi = tid >> 3, dg = tid & 7;
    float4 acc = make_float4(0.f, 0.f, 0.f, 0.f);
    const float* Lp = sP + qi * LP;
    const float4* V4 = reinterpret_cast<const float4*>(sV) + dg;
#pragma unroll 4
    for (int w = 0; w < WS2; w++) {
        float p = Lp[w];
        float4 v = V4[w * 8];
        acc.x = fmaf(p, v.x, acc.x);
        acc.y = fmaf(p, v.y, acc.y);
        acc.z = fmaf(p, v.z, acc.z);
        acc.w = fmaf(p, v.w, acc.w);
    }
    float4* dst = reinterpret_cast<float4*>(
        g_ctx + ((size_t)(q0 + qi) * NB + n) * CH + h * HD + dg * 4);
    float4 c = *dst;
    c.x += acc.x; c.y += acc.y; c.z += acc.z; c.w += acc.w;
    *dst = c;
}

// ============================================================
// Kernel 5: output projection (unchanged).
// ============================================================
__global__ void __launch_bounds__(256) outproj_kernel(
    const float* __restrict__ Wp, const float* __restrict__ bp,
    float* __restrict__ out)
{
    __shared__ __align__(16) float As[64][32];
    __shared__ __align__(16) float BsT[64][33];

    int r0 = blockIdx.y * 64, o0 = blockIdx.x * 64;
    int tid = threadIdx.x;
    int tx = tid & 15, ty = tid >> 4;

    float acc[4][4] = {};

    for (int k0 = 0; k0 < CH; k0 += 32) {
#pragma unroll
        for (int s = 0; s < 8; s++) {
            int idx = tid + s * 256;
            int row = idx >> 5, col = idx & 31;
            As[row][col]  = g_ctx[(size_t)(r0 + row) * CH + k0 + col];
            BsT[row][col] = Wp[(size_t)(o0 + row) * CH + k0 + col];
        }
        __syncthreads();
#pragma unroll
        for (int cc = 0; cc < 32; cc++) {
            float aa[4], bb[4];
#pragma unroll
            for (int i = 0; i < 4; i++) aa[i] = As[ty * 4 + i][cc];
#pragma unroll
            for (int j = 0; j < 4; j++) bb[j] = BsT[tx * 4 + j][cc];
#pragma unroll
            for (int i = 0; i < 4; i++)
#pragma unroll
                for (int j = 0; j < 4; j++)
                    acc[i][j] = fmaf(aa[i], bb[j], acc[i][j]);
        }
        __syncthreads();
    }

#pragma unroll
    for (int i = 0; i < 4; i++) {
        int r = r0 + ty * 4 + i;
#pragma unroll
        for (int j = 0; j < 4; j++) {
            int o = o0 + tx * 4 + j;
            out[(size_t)r * CH + o] = acc[i][j] + bp[o];
        }
    }
}

// ============================================================
extern "C" void kernel_launch(void* const* d_in, const int* in_sizes, int n_in,
                              void* d_out, int out_size)
{
    const float* q    = (const float*)d_in[0];
    const float* k    = (const float*)d_in[1];
    const float* v    = (const float*)d_in[2];
    const float* Wq   = (const float*)d_in[3];
    const float* bq   = (const float*)d_in[4];
    const float* Wk   = (const float*)d_in[5];
    const float* bk   = (const float*)d_in[6];
    const float* Wv   = (const float*)d_in[7];
    const float* bv   = (const float*)d_in[8];
    const float* relw = (const float*)d_in[9];
    const float* relb = (const float*)d_in[10];
    const float* relv = (const float*)d_in[11];
    const float* Wp   = (const float*)d_in[12];
    const float* bp   = (const float*)d_in[13];
    (void)in_sizes; (void)n_in;

    float* out  = (float*)d_out;
    float* attn = (out_size >= OUT_ELEMS + ATTN_ELEMS) ? (out + OUT_ELEMS) : nullptr;

    static bool s_init = false;
    if (!s_init) {
        cudaFuncSetAttribute(abgemm_kernel,
                             cudaFuncAttributeMaxDynamicSharedMemorySize, AB_BYTES);
        s_init = true;
    }

    float* p_dst;
    cudaGetSymbolAddress((void**)&p_dst, g_pb);
    if (attn) p_dst = attn;

    proj_kernel<<<dim3(25, 2, 6), 256>>>(q, k, v, Wq, bq, Wk, bk, Wv, bv);
    relgemm_kernel<<<dim3(25, NHD, NB), 256>>>(relw, relb);
    attn_kernel<<<dim3(HI, NHD, NB), 320>>>(p_dst);
    abgemm_kernel<<<dim3(25, NHD, NB), 512, AB_BYTES>>>(relv, p_dst);
    outproj_kernel<<<dim3(4, 50), 256>>>(Wp, bp, out);
}

// round 11
// speedup vs baseline: 1.3892x; 1.3892x over previous
#include <cuda_runtime.h>
#include <math.h>

#define NB   2
#define NHD  8
#define HD   32
#define CH   256
#define HI   40
#define WIM  40
#define HW   1600
#define WSZ  15
#define WS2  225
#define NEGV 1e8f
#define INV_T 0.17677669529663687f   // 1/sqrt(32)

#define OUT_ELEMS  (HW*NB*CH)            // 819200
#define ATTN_ELEMS (NB*NHD*HW*WS2)       // 5760000

// ---- scratch ----
__device__ float g_qp[NB*NHD*HW*HD];     // [n][h][q][d] unscaled
__device__ float g_kp[NB*NHD*HW*HD];     // [n][h][j][d] scaled by 1/T
__device__ float g_vp[NB*NHD*HW*HD];
__device__ float g_ctx[HW*NB*CH];        // [i][n][c]
__device__ float g_rel[NB*NHD*WS2*HW];   // [n][h][w][q]  rel logits
__device__ float g_pb[ATTN_ELEMS];       // fallback p storage

// ============================================================
// Kernel 1: fused QKV projection (unchanged).
// ============================================================
__global__ void __launch_bounds__(256, 2) proj_kernel(
    const float* __restrict__ q, const float* __restrict__ k, const float* __restrict__ v,
    const float* __restrict__ Wq, const float* __restrict__ bq,
    const float* __restrict__ Wk, const float* __restrict__ bk,
    const float* __restrict__ Wv, const float* __restrict__ bv)
{
    __shared__ __align__(16) float Ws[128 * 33];
    __shared__ __align__(16) float Bs[32][64];

    int z = blockIdx.z;
    int n = z & 1, t = z >> 1;
    const float* X; const float* W; const float* b; float* Y; float scale;
    if (t == 0)      { X = q; W = Wq; b = bq; Y = g_qp; scale = 1.0f;  }
    else if (t == 1) { X = k; W = Wk; b = bk; Y = g_kp; scale = INV_T; }
    else             { X = v; W = Wv; b = bv; Y = g_vp; scale = 1.0f;  }
    X += (size_t)n * CH * HW;

    int o0 = blockIdx.y * 128, p0 = blockIdx.x * 64;
    int tid = threadIdx.x;
    int tx = tid & 15, ty = tid >> 4;

    float acc[8][4] = {};

    for (int k0 = 0; k0 < CH; k0 += 32) {
#pragma unroll
        for (int s = 0; s < 16; s++) {
            int idx = tid + s * 256;
            int row = idx >> 5, col = idx & 31;
            Ws[row * 33 + col] = W[(size_t)(o0 + row) * CH + k0 + col];
        }
#pragma unroll
        for (int s = 0; s < 8; s++) {
            int idx = tid + s * 256;
            int col = idx & 63, row = idx >> 6;
            Bs[row][col] = X[(size_t)(k0 + row) * HW + p0 + col];
        }
        __syncthreads();
#pragma unroll
        for (int cc = 0; cc < 32; cc++) {
            float4 b4 = *reinterpret_cast<const float4*>(&Bs[cc][tx * 4]);
            float bb[4] = {b4.x, b4.y, b4.z, b4.w};
            float aa[8];
#pragma unroll
            for (int i = 0; i < 8; i++) aa[i] = Ws[(ty * 8 + i) * 33 + cc];
#pragma unroll
            for (int i = 0; i < 8; i++)
#pragma unroll
                for (int j = 0; j < 4; j++)
                    acc[i][j] = fmaf(aa[i], bb[j], acc[i][j]);
        }
        __syncthreads();
    }

#pragma unroll
    for (int i = 0; i < 8; i++) {
        int o = o0 + ty * 8 + i;
        int h = o >> 5, d = o & 31;
        float bias = b[o];
#pragma unroll
        for (int j = 0; j < 4; j++) {
            int p = p0 + tx * 4 + j;
            float val = (acc[i][j] + bias) * scale;
            Y[((size_t)(n * NHD + h) * HW + p) * HD + d] = val;
        }
    }
}

// ============================================================
// Kernel 2: rel logits GEMM (proven in R9).
// rel[n,h,w,q] = q_unscaled . relw[h,w] + relb[h,w]
// ============================================================
__global__ void __launch_bounds__(256) relgemm_kernel(
    const float* __restrict__ relw_g,   // [NHD][WS2][HD]
    const float* __restrict__ relb_g)   // [NHD][WS2]
{
    __shared__ __align__(16) float sW[WS2 * HD];   // [w][d]
    __shared__ float sb[WS2];

    int q0 = blockIdx.x * 64, h = blockIdx.y, n = blockIdx.z;
    int tid = threadIdx.x;
    int nh = n * NHD + h;

    {
        const float4* src = reinterpret_cast<const float4*>(relw_g + (size_t)h * WS2 * HD);
        float4* dst = reinterpret_cast<float4*>(sW);
        for (int i = tid; i < WS2 * HD / 4; i += 256) dst[i] = src[i];
        const float* bs = relb_g + (size_t)h * WS2;
        for (int i = tid; i < WS2; i += 256) sb[i] = bs[i];
    }
    __syncthreads();

    int qi = tid & 63, wg = tid >> 6;
    int qq = q0 + qi;
    float4 qv[8];
    {
        const float4* qsrc = reinterpret_cast<const float4*>(
            g_qp + (size_t)(nh * HW + qq) * HD);
#pragma unroll
        for (int u = 0; u < 8; u++) qv[u] = qsrc[u];
    }
    float* dst = g_rel + (size_t)nh * WS2 * HW + qq;
#pragma unroll 1
    for (int w = wg; w < WS2; w += 4) {
        const float4* r4 = reinterpret_cast<const float4*>(sW + w * HD);
        float4 a = make_float4(0.f, 0.f, 0.f, 0.f);
#pragma unroll
        for (int u = 0; u < 8; u++) {
            float4 rv = r4[u], qu = qv[u];
            a.x = fmaf(qu.x, rv.x, a.x);
            a.y = fmaf(qu.y, rv.y, a.y);
            a.z = fmaf(qu.z, rv.z, a.z);
            a.w = fmaf(qu.w, rv.w, a.w);
        }
        dst[(size_t)w * HW] = (a.x + a.y) + (a.z + a.w) + sb[w];
    }
}

// ============================================================
// Kernel 3: local attention (R8 skeleton, rel FMAs removed).
// Block per (qy pair, h, n). 640 threads.
// ============================================================
#define GQ    2
#define QG    80
#define KROWS 16
#define PADW  54
#define KP    36
#define LP    228
#define SM_K      0                          // 16*54*36 = 31104
#define SM_L      31104                      // 80*228   = 18240
#define SM_FLOATS 49344
#define SM_BYTES  (SM_FLOATS * 4)            // 197376 B

__global__ void __launch_bounds__(640, 1) attn_kernel(float* __restrict__ p_out)
{
    int qy0 = blockIdx.x * GQ, h = blockIdx.y, n = blockIdx.z;
    int tid = threadIdx.x;
    extern __shared__ __align__(16) float sm[];
    float* sK = sm + SM_K;
    float* sL = sm + SM_L;

    int nh = n * NHD + h;
    int nh_base = nh * HW;
    const float4 z4 = make_float4(0.f, 0.f, 0.f, 0.f);

    // ---- stage K (16 rows, OOB rows -> 0) + pad cols ----
    for (int i = tid; i < KROWS * 320; i += 640) {
        int r = i / 320, rem = i - r * 320;
        int ky = qy0 - 7 + r;
        float4 val = z4;
        if ((unsigned)ky < HI)
            val = reinterpret_cast<const float4*>(
                      g_kp + (size_t)(nh_base + ky * WIM) * HD)[rem];
        int kx = rem >> 3, u = rem & 7;
        *reinterpret_cast<float4*>(sK + (r * PADW + 7 + kx) * KP + 4 * u) = val;
    }
    for (int i = tid; i < KROWS * 112; i += 640) {
        int r = i / 112, rem = i - r * 112;
        int c = rem >> 3, u = rem & 7;
        int col = (c < 7) ? c : (c + 40);             // pads: 0..6, 47..53
        *reinterpret_cast<float4*>(sK + (r * PADW + col) * KP + 4 * u) = z4;
    }
    __syncthreads();

    // ---- logits: thread = (qg = tid%80, wg = tid/80 in 0..7) ----
    {
        int qg = tid % QG;
        int wg = tid / QG;
        int qyl = (qg >= 40) ? 1 : 0;
        int qx = qg - qyl * 40;
        float4 qv[8];
        {
            const float4* qsrc = reinterpret_cast<const float4*>(
                g_qp + (size_t)(nh_base + qy0 * WIM + qg) * HD);
#pragma unroll
            for (int u = 0; u < 8; u++) qv[u] = qsrc[u];
        }
        const float* relp = g_rel + (size_t)nh * WS2 * HW + qy0 * WIM + qg;
        int wy = 0, wx = wg;
#pragma unroll 1
        for (int w = wg; w < WS2; w += 8) {
            int ky = qy0 + qyl + wy - 7, kx = qx + wx - 7;
            bool img = ((unsigned)ky < HI) & ((unsigned)kx < WIM);
            const float4* k4 = reinterpret_cast<const float4*>(
                sK + ((qyl + wy) * PADW + qx + wx) * KP);
            float rel = __ldg(relp + (size_t)w * HW);
            float4 a = z4;
#pragma unroll
            for (int u = 0; u < 8; u++) {
                float4 kv = k4[u], qq = qv[u];
                a.x = fmaf(qq.x, kv.x, a.x);
                a.y = fmaf(qq.y, kv.y, a.y);
                a.z = fmaf(qq.z, kv.z, a.z);
                a.w = fmaf(qq.w, kv.w, a.w);
            }
            float qk = (a.x + a.y) + (a.z + a.w);
            sL[qg * LP + w] = (img ? qk : -NEGV) + rel;
            wx += 8;
            if (wx >= WSZ) { wx -= WSZ; wy++; }
        }
    }
    __syncthreads();

    // ---- V staging (sK region; disjoint from softmax's sL) ----
    for (int i = tid; i < KROWS * 320; i += 640) {
        int r = i / 320, rem = i - r * 320;
        int ky = qy0 - 7 + r;
        float4 val = z4;
        if ((unsigned)ky < HI)
            val = reinterpret_cast<const float4*>(
                      g_vp + (size_t)(nh_base + ky * WIM) * HD)[rem];
        reinterpret_cast<float4*>(sK + (r * PADW + 7) * HD)[rem] = val;
    }
    for (int i = tid; i < KROWS * 112; i += 640) {    // V pad cols (pitch 32)
        int r = i / 112, rem = i - r * 112;
        int c = rem >> 3, u = rem & 7;
        int col = (c < 7) ? c : (c + 40);
        *reinterpret_cast<float4*>(sK + (r * PADW + col) * HD + 4 * u) = z4;
    }

    // ---- softmax: 20 warps x 4 queries (sL only) ----
    {
        int warp = tid >> 5, lane = tid & 31;
#pragma unroll 1
        for (int qq = 0; qq < 4; qq++) {
            int qg = warp * 4 + qq;
            float* Lp = sL + qg * LP;
            float vals[8];
            float m = -3.0e38f;
#pragma unroll
            for (int u = 0; u < 8; u++) {
                int w = lane + u * 32;
                vals[u] = (w < WS2) ? Lp[w] : -3.0e38f;
                m = fmaxf(m, vals[u]);
            }
#pragma unroll
            for (int off = 16; off > 0; off >>= 1)
                m = fmaxf(m, __shfl_xor_sync(0xffffffffu, m, off));
            float s = 0.0f;
#pragma unroll
            for (int u = 0; u < 8; u++) { float p = __expf(vals[u] - m); vals[u] = p; s += p; }
#pragma unroll
            for (int off = 16; off > 0; off >>= 1)
                s += __shfl_xor_sync(0xffffffffu, s, off);
            float inv = 1.0f / s;
            float* gp = p_out + (size_t)(nh_base + qy0 * WIM + qg) * WS2;
#pragma unroll
            for (int u = 0; u < 8; u++) {
                int w = lane + u * 32;
                if (w < WS2) {
                    float p = vals[u] * inv;
                    Lp[w] = p;
                    gp[w] = p;
                }
            }
        }
    }
    __syncthreads();

    // ---- V aggregation: warp = 4 consecutive queries, lane = d ----
    {
        int warp = tid >> 5, lane = tid & 31;
        int q0 = warp * 4;
        int qyl = (q0 >= 40) ? 1 : 0;
        int qx0 = q0 - qyl * 40;
        float av[4] = {0.f, 0.f, 0.f, 0.f};
        int wy = 0, wx = 0;
#pragma unroll 1
        for (int g = 0; g < 56; g++) {
            int w4 = g * 4;
#pragma unroll
            for (int j = 0; j < 4; j++) {
                float4 p4 = *reinterpret_cast<const float4*>(sL + (q0 + j) * LP + w4);
                float ps[4] = {p4.x, p4.y, p4.z, p4.w};
#pragma unroll
                for (int t = 0; t < 4; t++) {
                    int wx_t = wx + t, wy_t = wy;
                    if (wx_t >= WSZ) { wx_t -= WSZ; wy_t++; }
                    const float* vb = sK + ((qyl + wy_t) * PADW + qx0 + j + wx_t) * HD + lane;
                    av[j] = fmaf(ps[t], *vb, av[j]);
                }
            }
            wx += 4;
            if (wx >= WSZ) { wx -= WSZ; wy++; }
        }
        {   // tail w = 224 (wy=14, wx=14)
#pragma unroll
            for (int j = 0; j < 4; j++) {
                float p = sL[(q0 + j) * LP + 224];
                const float* vb = sK + ((qyl + 14) * PADW + qx0 + j + 14) * HD + lane;
                av[j] = fmaf(p, *vb, av[j]);
            }
        }
#pragma unroll
        for (int j = 0; j < 4; j++) {
            int iy = (qy0 + qyl) * WIM + qx0 + j;
            g_ctx[((size_t)iy * NB + n) * CH + h * HD + lane] = av[j];
        }
    }
}

// ============================================================
// Kernel 4: agg_bias GEMM (rebuilt):
// ctx[q,n,h*32+d] += sum_w p[n,h,q,w] * relv[h,d,w]
// 256 thr = (qi 0..63, dg 0..3), 8 d-outputs per thread.
// ============================================================
#define AB_SP      0                    // 64*228 = 14592
#define AB_SV      14592                // [w][32] 225*32 = 7200
#define AB_FLOATS  21792
#define AB_BYTES   (AB_FLOATS * 4)      // 87168

__global__ void __launch_bounds__(256) abgemm_kernel(
    const float* __restrict__ relv_g,   // [NHD][HD][WS2]
    const float* __restrict__ p_src)    // [n,h,q,w]
{
    extern __shared__ __align__(16) float sm[];
    float* sP = sm + AB_SP;
    float* sV = sm + AB_SV;

    int q0 = blockIdx.x * 64, h = blockIdx.y, n = blockIdx.z;
    int tid = threadIdx.x;
    int nh = n * NHD + h;

    {
        const float* src = p_src + ((size_t)nh * HW + q0) * WS2;
        for (int i = tid; i < 64 * WS2; i += 256) {
            int r = i / WS2, w = i - r * WS2;
            sP[r * LP + w] = src[i];
        }
        const float* rv = relv_g + (size_t)h * HD * WS2;
        for (int i = tid; i < HD * WS2; i += 256) {
            int d = i / WS2, w = i - d * WS2;
            sV[w * HD + d] = rv[i];
        }
    }
    __syncthreads();

    int qi = tid >> 2, dg = tid & 3;
    int d0 = dg * 8;
    const float* Lp = sP + qi * LP;
    float a[8] = {};
#pragma unroll 1
    for (int c = 0; c < 56; c++) {
        int w4 = c * 4;
        float4 p4 = *reinterpret_cast<const float4*>(Lp + w4);
        float ps[4] = {p4.x, p4.y, p4.z, p4.w};
#pragma unroll
        for (int t = 0; t < 4; t++) {
            const float* vb = sV + (w4 + t) * HD + d0;
            float4 va = *reinterpret_cast<const float4*>(vb);
            float4 vbb = *reinterpret_cast<const float4*>(vb + 4);
            float p = ps[t];
            a[0] = fmaf(p, va.x, a[0]);
            a[1] = fmaf(p, va.y, a[1]);
            a[2] = fmaf(p, va.z, a[2]);
            a[3] = fmaf(p, va.w, a[3]);
            a[4] = fmaf(p, vbb.x, a[4]);
            a[5] = fmaf(p, vbb.y, a[5]);
            a[6] = fmaf(p, vbb.z, a[6]);
            a[7] = fmaf(p, vbb.w, a[7]);
        }
    }
    {   // tail w = 224
        float p = Lp[224];
        const float* vb = sV + 224 * HD + d0;
#pragma unroll
        for (int e = 0; e < 8; e++) a[e] = fmaf(p, vb[e], a[e]);
    }
    float* dst = g_ctx + ((size_t)(q0 + qi) * NB + n) * CH + h * HD + d0;
    float4 c0 = *reinterpret_cast<float4*>(dst);
    float4 c1 = *reinterpret_cast<float4*>(dst + 4);
    c0.x += a[0]; c0.y += a[1]; c0.z += a[2]; c0.w += a[3];
    c1.x += a[4]; c1.y += a[5]; c1.z += a[6]; c1.w += a[7];
    *reinterpret_cast<float4*>(dst) = c0;
    *reinterpret_cast<float4*>(dst + 4) = c1;
}

// ============================================================
// Kernel 5: output projection (unchanged).
// ============================================================
__global__ void __launch_bounds__(256) outproj_kernel(
    const float* __restrict__ Wp, const float* __restrict__ bp,
    float* __restrict__ out)
{
    __shared__ __align__(16) float As[64][32];
    __shared__ __align__(16) float BsT[64][33];

    int r0 = blockIdx.y * 64, o0 = blockIdx.x * 64;
    int tid = threadIdx.x;
    int tx = tid & 15, ty = tid >> 4;

    float acc[4][4] = {};

    for (int k0 = 0; k0 < CH; k0 += 32) {
#pragma unroll
        for (int s = 0; s < 8; s++) {
            int idx = tid + s * 256;
            int row = idx >> 5, col = idx & 31;
            As[row][col]  = g_ctx[(size_t)(r0 + row) * CH + k0 + col];
            BsT[row][col] = Wp[(size_t)(o0 + row) * CH + k0 + col];
        }
        __syncthreads();
#pragma unroll
        for (int cc = 0; cc < 32; cc++) {
            float aa[4], bb[4];
#pragma unroll
            for (int i = 0; i < 4; i++) aa[i] = As[ty * 4 + i][cc];
#pragma unroll
            for (int j = 0; j < 4; j++) bb[j] = BsT[tx * 4 + j][cc];
#pragma unroll
            for (int i = 0; i < 4; i++)
#pragma unroll
                for (int j = 0; j < 4; j++)
                    acc[i][j] = fmaf(aa[i], bb[j], acc[i][j]);
        }
        __syncthreads();
    }

#pragma unroll
    for (int i = 0; i < 4; i++) {
        int r = r0 + ty * 4 + i;
#pragma unroll
        for (int j = 0; j < 4; j++) {
            int o = o0 + tx * 4 + j;
            out[(size_t)r * CH + o] = acc[i][j] + bp[o];
        }
    }
}

// ============================================================
extern "C" void kernel_launch(void* const* d_in, const int* in_sizes, int n_in,
                              void* d_out, int out_size)
{
    const float* q    = (const float*)d_in[0];
    const float* k    = (const float*)d_in[1];
    const float* v    = (const float*)d_in[2];
    const float* Wq   = (const float*)d_in[3];
    const float* bq   = (const float*)d_in[4];
    const float* Wk   = (const float*)d_in[5];
    const float* bk   = (const float*)d_in[6];
    const float* Wv   = (const float*)d_in[7];
    const float* bv   = (const float*)d_in[8];
    const float* relw = (const float*)d_in[9];
    const float* relb = (const float*)d_in[10];
    const float* relv = (const float*)d_in[11];
    const float* Wp   = (const float*)d_in[12];
    const float* bp   = (const float*)d_in[13];
    (void)in_sizes; (void)n_in;

    float* out  = (float*)d_out;
    float* attn = (out_size >= OUT_ELEMS + ATTN_ELEMS) ? (out + OUT_ELEMS) : nullptr;

    static bool s_init = false;
    if (!s_init) {
        cudaFuncSetAttribute(attn_kernel,
                             cudaFuncAttributeMaxDynamicSharedMemorySize, SM_BYTES);
        cudaFuncSetAttribute(abgemm_kernel,
                             cudaFuncAttributeMaxDynamicSharedMemorySize, AB_BYTES);
        s_init = true;
    }

    float* p_dst;
    cudaGetSymbolAddress((void**)&p_dst, g_pb);
    if (attn) p_dst = attn;

    proj_kernel<<<dim3(25, 2, 6), 256>>>(q, k, v, Wq, bq, Wk, bk, Wv, bv);
    relgemm_kernel<<<dim3(25, NHD, NB), 256>>>(relw, relb);
    attn_kernel<<<dim3(HI / GQ, NHD, NB), 640, SM_BYTES>>>(p_dst);
    abgemm_kernel<<<dim3(25, NHD, NB), 256, AB_BYTES>>>(relv, p_dst);
    outproj_kernel<<<dim3(4, 50), 256>>>(Wp, bp, out);
}

// round 12
// speedup vs baseline: 1.7285x; 1.2442x over previous
#include <cuda_runtime.h>
#include <math.h>

#define NB   2
#define NHD  8
#define HD   32
#define CH   256
#define HI   40
#define WIM  40
#define HW   1600
#define WSZ  15
#define WS2  225
#define NEGV 1e8f
#define INV_T 0.17677669529663687f   // 1/sqrt(32)

#define OUT_ELEMS  (HW*NB*CH)            // 819200
#define ATTN_ELEMS (NB*NHD*HW*WS2)       // 5760000

// ---- scratch ----
__device__ float g_qp[NB*NHD*HW*HD];     // [n][h][q][d] unscaled
__device__ float g_kp[NB*NHD*HW*HD];     // [n][h][j][d] scaled by 1/T
__device__ float g_vp[NB*NHD*HW*HD];
__device__ float g_ctx[HW*NB*CH];        // [i][n][c]
__device__ float g_rel[NB*NHD*WS2*HW];   // [n][h][w][q]  rel logits
__device__ float g_pb[ATTN_ELEMS];       // fallback p storage

// ============================================================
// Kernel 1: fused QKV projection (unchanged).
// ============================================================
__global__ void __launch_bounds__(256, 2) proj_kernel(
    const float* __restrict__ q, const float* __restrict__ k, const float* __restrict__ v,
    const float* __restrict__ Wq, const float* __restrict__ bq,
    const float* __restrict__ Wk, const float* __restrict__ bk,
    const float* __restrict__ Wv, const float* __restrict__ bv)
{
    __shared__ __align__(16) float Ws[128 * 33];
    __shared__ __align__(16) float Bs[32][64];

    int z = blockIdx.z;
    int n = z & 1, t = z >> 1;
    const float* X; const float* W; const float* b; float* Y; float scale;
    if (t == 0)      { X = q; W = Wq; b = bq; Y = g_qp; scale = 1.0f;  }
    else if (t == 1) { X = k; W = Wk; b = bk; Y = g_kp; scale = INV_T; }
    else             { X = v; W = Wv; b = bv; Y = g_vp; scale = 1.0f;  }
    X += (size_t)n * CH * HW;

    int o0 = blockIdx.y * 128, p0 = blockIdx.x * 64;
    int tid = threadIdx.x;
    int tx = tid & 15, ty = tid >> 4;

    float acc[8][4] = {};

    for (int k0 = 0; k0 < CH; k0 += 32) {
#pragma unroll
        for (int s = 0; s < 16; s++) {
            int idx = tid + s * 256;
            int row = idx >> 5, col = idx & 31;
            Ws[row * 33 + col] = W[(size_t)(o0 + row) * CH + k0 + col];
        }
#pragma unroll
        for (int s = 0; s < 8; s++) {
            int idx = tid + s * 256;
            int col = idx & 63, row = idx >> 6;
            Bs[row][col] = X[(size_t)(k0 + row) * HW + p0 + col];
        }
        __syncthreads();
#pragma unroll
        for (int cc = 0; cc < 32; cc++) {
            float4 b4 = *reinterpret_cast<const float4*>(&Bs[cc][tx * 4]);
            float bb[4] = {b4.x, b4.y, b4.z, b4.w};
            float aa[8];
#pragma unroll
            for (int i = 0; i < 8; i++) aa[i] = Ws[(ty * 8 + i) * 33 + cc];
#pragma unroll
            for (int i = 0; i < 8; i++)
#pragma unroll
                for (int j = 0; j < 4; j++)
                    acc[i][j] = fmaf(aa[i], bb[j], acc[i][j]);
        }
        __syncthreads();
    }

#pragma unroll
    for (int i = 0; i < 8; i++) {
        int o = o0 + ty * 8 + i;
        int h = o >> 5, d = o & 31;
        float bias = b[o];
#pragma unroll
        for (int j = 0; j < 4; j++) {
            int p = p0 + tx * 4 + j;
            float val = (acc[i][j] + bias) * scale;
            Y[((size_t)(n * NHD + h) * HW + p) * HD + d] = val;
        }
    }
}

// ============================================================
// Kernel 2: rel logits GEMM.
// ============================================================
__global__ void __launch_bounds__(256) relgemm_kernel(
    const float* __restrict__ relw_g,   // [NHD][WS2][HD]
    const float* __restrict__ relb_g)   // [NHD][WS2]
{
    __shared__ __align__(16) float sW[WS2 * HD];   // [w][d]
    __shared__ float sb[WS2];

    int q0 = blockIdx.x * 64, h = blockIdx.y, n = blockIdx.z;
    int tid = threadIdx.x;
    int nh = n * NHD + h;

    {
        const float4* src = reinterpret_cast<const float4*>(relw_g + (size_t)h * WS2 * HD);
        float4* dst = reinterpret_cast<float4*>(sW);
        for (int i = tid; i < WS2 * HD / 4; i += 256) dst[i] = src[i];
        const float* bs = relb_g + (size_t)h * WS2;
        for (int i = tid; i < WS2; i += 256) sb[i] = bs[i];
    }
    __syncthreads();

    int qi = tid & 63, wg = tid >> 6;
    int qq = q0 + qi;
    float4 qv[8];
    {
        const float4* qsrc = reinterpret_cast<const float4*>(
            g_qp + (size_t)(nh * HW + qq) * HD);
#pragma unroll
        for (int u = 0; u < 8; u++) qv[u] = qsrc[u];
    }
    float* dst = g_rel + (size_t)nh * WS2 * HW + qq;
#pragma unroll 1
    for (int w = wg; w < WS2; w += 4) {
        const float4* r4 = reinterpret_cast<const float4*>(sW + w * HD);
        float4 a = make_float4(0.f, 0.f, 0.f, 0.f);
#pragma unroll
        for (int u = 0; u < 8; u++) {
            float4 rv = r4[u], qu = qv[u];
            a.x = fmaf(qu.x, rv.x, a.x);
            a.y = fmaf(qu.y, rv.y, a.y);
            a.z = fmaf(qu.z, rv.z, a.z);
            a.w = fmaf(qu.w, rv.w, a.w);
        }
        dst[(size_t)w * HW] = (a.x + a.y) + (a.z + a.w) + sb[w];
    }
}

// ============================================================
// Kernel 3: local attention. Block per (qy pair, h, n). 640 threads.
// sL: 16 slots per wy (pitch 240/query); wx=15 ghost slot holds p=0.
// Fused agg = PV + rel_v bias, ky-convolution, shared V register tiles.
// ============================================================
#define GQ    2
#define QG    80
#define KROWS 16
#define PADW  54
#define KP    36
#define LPQ   240
#define SM_K      0                          // 16*54*36 = 31104
#define SM_L      31104                      // 80*240   = 19200
#define SM_V      50304                      // 226*32   = 7232
#define SM_FLOATS 57536
#define SM_BYTES  (SM_FLOATS * 4)            // 230144 B

__global__ void __launch_bounds__(640, 1) attn_kernel(
    const float* __restrict__ relv_g,   // [NHD][HD][WS2]
    float* __restrict__ p_out)
{
    int qy0 = blockIdx.x * GQ, h = blockIdx.y, n = blockIdx.z;
    int tid = threadIdx.x;
    extern __shared__ __align__(16) float sm[];
    float* sK = sm + SM_K;
    float* sL = sm + SM_L;
    float* sV = sm + SM_V;

    int nh = n * NHD + h;
    int nh_base = nh * HW;
    const float4 z4 = make_float4(0.f, 0.f, 0.f, 0.f);

    // ---- stage K (16 rows, OOB rows -> 0) + pad cols ----
    for (int i = tid; i < KROWS * 320; i += 640) {
        int r = i / 320, rem = i - r * 320;
        int ky = qy0 - 7 + r;
        float4 val = z4;
        if ((unsigned)ky < HI)
            val = reinterpret_cast<const float4*>(
                      g_kp + (size_t)(nh_base + ky * WIM) * HD)[rem];
        int kx = rem >> 3, u = rem & 7;
        *reinterpret_cast<float4*>(sK + (r * PADW + 7 + kx) * KP + 4 * u) = val;
    }
    for (int i = tid; i < KROWS * 112; i += 640) {
        int r = i / 112, rem = i - r * 112;
        int c = rem >> 3, u = rem & 7;
        int col = (c < 7) ? c : (c + 40);             // pads: 0..6, 47..53
        *reinterpret_cast<float4*>(sK + (r * PADW + col) * KP + 4 * u) = z4;
    }
    __syncthreads();

    // ---- logits: thread = (qg = tid%80, wg = tid/80 in 0..7) ----
    {
        int qg = tid % QG;
        int wg = tid / QG;
        int qyl = (qg >= 40) ? 1 : 0;
        int qx = qg - qyl * 40;
        float4 qv[8];
        {
            const float4* qsrc = reinterpret_cast<const float4*>(
                g_qp + (size_t)(nh_base + qy0 * WIM + qg) * HD);
#pragma unroll
            for (int u = 0; u < 8; u++) qv[u] = qsrc[u];
        }
        const float* relp = g_rel + (size_t)nh * WS2 * HW + qy0 * WIM + qg;
        int wy = 0, wx = wg;
#pragma unroll 1
        for (int w = wg; w < WS2; w += 8) {
            int ky = qy0 + qyl + wy - 7, kx = qx + wx - 7;
            bool img = ((unsigned)ky < HI) & ((unsigned)kx < WIM);
            const float4* k4 = reinterpret_cast<const float4*>(
                sK + ((qyl + wy) * PADW + qx + wx) * KP);
            float rel = __ldg(relp + (size_t)w * HW);
            float4 a = z4;
#pragma unroll
            for (int u = 0; u < 8; u++) {
                float4 kv = k4[u], qq = qv[u];
                a.x = fmaf(qq.x, kv.x, a.x);
                a.y = fmaf(qq.y, kv.y, a.y);
                a.z = fmaf(qq.z, kv.z, a.z);
                a.w = fmaf(qq.w, kv.w, a.w);
            }
            float qk = (a.x + a.y) + (a.z + a.w);
            sL[qg * LPQ + wy * 16 + wx] = (img ? qk : -NEGV) + rel;
            wx += 8;
            if (wx >= WSZ) { wx -= WSZ; wy++; }
        }
    }
    __syncthreads();

    // ---- V staging (pitch 32) + relv [d][w] -> sV [w][d] ----
    for (int i = tid; i < KROWS * 320; i += 640) {
        int r = i / 320, rem = i - r * 320;
        int ky = qy0 - 7 + r;
        float4 val = z4;
        if ((unsigned)ky < HI)
            val = reinterpret_cast<const float4*>(
                      g_vp + (size_t)(nh_base + ky * WIM) * HD)[rem];
        reinterpret_cast<float4*>(sK + (r * PADW + 7) * HD)[rem] = val;
    }
    for (int i = tid; i < KROWS * 112; i += 640) {    // V pad cols
        int r = i / 112, rem = i - r * 112;
        int c = rem >> 3, u = rem & 7;
        int col = (c < 7) ? c : (c + 40);
        *reinterpret_cast<float4*>(sK + (r * PADW + col) * HD + 4 * u) = z4;
    }
    {
        const float* rv = relv_g + (size_t)h * HD * WS2;
        for (int i = tid; i < HD * WS2; i += 640) {
            int d = i / WS2, w = i - d * WS2;
            sV[w * HD + d] = rv[i];
        }
        if (tid < HD) sV[WS2 * HD + tid] = 0.0f;      // ghost relv row (ky=14,wx=15)
    }

    // ---- softmax: 20 warps x 4 queries over the padded 240-slot rows ----
    {
        int warp = tid >> 5, lane = tid & 31;
#pragma unroll 1
        for (int qq = 0; qq < 4; qq++) {
            int qg = warp * 4 + qq;
            float* Lp = sL + qg * LPQ;
            float vals[8];
            float m = -3.0e38f;
#pragma unroll
            for (int u = 0; u < 8; u++) {
                int slot = lane + u * 32;
                bool ok = (slot < LPQ) && ((slot & 15) != 15);
                vals[u] = ok ? Lp[slot] : -3.0e38f;
                m = fmaxf(m, vals[u]);
            }
#pragma unroll
            for (int off = 16; off > 0; off >>= 1)
                m = fmaxf(m, __shfl_xor_sync(0xffffffffu, m, off));
            float s = 0.0f;
#pragma unroll
            for (int u = 0; u < 8; u++) { float p = __expf(vals[u] - m); vals[u] = p; s += p; }
#pragma unroll
            for (int off = 16; off > 0; off >>= 1)
                s += __shfl_xor_sync(0xffffffffu, s, off);
            float inv = 1.0f / s;
            float* gp = p_out + (size_t)(nh_base + qy0 * WIM + qg) * WS2;
#pragma unroll
            for (int u = 0; u < 8; u++) {
                int slot = lane + u * 32;
                if (slot < LPQ) {
                    float p = vals[u] * inv;          // ghost slots -> exactly 0
                    Lp[slot] = p;
                    if ((slot & 15) != 15)
                        gp[slot - (slot >> 4)] = p;   // w = wy*15+wx
                }
            }
        }
    }
    __syncthreads();

    // ---- fused aggregation: warp = 4 consecutive qx (one row), lane = d ----
    {
        int warp = tid >> 5, lane = tid & 31;
        int qyl = (warp >= 10) ? 1 : 0;
        int qx0 = (warp - qyl * 10) * 4;              // 0..36
        int qbase = qyl * 40 + qx0;
        float av[4] = {0.f, 0.f, 0.f, 0.f};
        float ab[4] = {0.f, 0.f, 0.f, 0.f};
#pragma unroll 1
        for (int ky = 0; ky < WSZ; ky++) {
            const float* vrow = sK + ((qyl + ky) * PADW + qx0) * HD + lane;
            float vv[19];
#pragma unroll
            for (int c = 0; c < 19; c++) vv[c] = vrow[c * HD];
            const float* rvrow = sV + ky * WSZ * HD + lane;
            float rvv[16];
#pragma unroll
            for (int t = 0; t < 16; t++) rvv[t] = rvrow[t * HD];
#pragma unroll
            for (int j = 0; j < 4; j++) {
                const float* Lp = sL + (qbase + j) * LPQ + ky * 16;
#pragma unroll
                for (int g = 0; g < 4; g++) {
                    float4 p4 = *reinterpret_cast<const float4*>(Lp + g * 4);
                    float pe[4] = {p4.x, p4.y, p4.z, p4.w};
#pragma unroll
                    for (int t = 0; t < 4; t++) {
                        int wx = g * 4 + t;           // 0..15 (wx=15: p==0)
                        av[j] = fmaf(pe[t], vv[j + wx], av[j]);
                        ab[j] = fmaf(pe[t], rvv[wx], ab[j]);
                    }
                }
            }
        }
#pragma unroll
        for (int j = 0; j < 4; j++) {
            int iy = (qy0 + qyl) * WIM + qx0 + j;
            g_ctx[((size_t)iy * NB + n) * CH + h * HD + lane] = av[j] + ab[j];
        }
    }
}

// ============================================================
// Kernel 4: output projection (unchanged).
// ============================================================
__global__ void __launch_bounds__(256) outproj_kernel(
    const float* __restrict__ Wp, const float* __restrict__ bp,
    float* __restrict__ out)
{
    __shared__ __align__(16) float As[64][32];
    __shared__ __align__(16) float BsT[64][33];

    int r0 = blockIdx.y * 64, o0 = blockIdx.x * 64;
    int tid = threadIdx.x;
    int tx = tid & 15, ty = tid >> 4;

    float acc[4][4] = {};

    for (int k0 = 0; k0 < CH; k0 += 32) {
#pragma unroll
        for (int s = 0; s < 8; s++) {
            int idx = tid + s * 256;
            int row = idx >> 5, col = idx & 31;
            As[row][col]  = g_ctx[(size_t)(r0 + row) * CH + k0 + col];
            BsT[row][col] = Wp[(size_t)(o0 + row) * CH + k0 + col];
        }
        __syncthreads();
#pragma unroll
        for (int cc = 0; cc < 32; cc++) {
            float aa[4], bb[4];
#pragma unroll
            for (int i = 0; i < 4; i++) aa[i] = As[ty * 4 + i][cc];
#pragma unroll
            for (int j = 0; j < 4; j++) bb[j] = BsT[tx * 4 + j][cc];
#pragma unroll
            for (int i = 0; i < 4; i++)
#pragma unroll
                for (int j = 0; j < 4; j++)
                    acc[i][j] = fmaf(aa[i], bb[j], acc[i][j]);
        }
        __syncthreads();
    }

#pragma unroll
    for (int i = 0; i < 4; i++) {
        int r = r0 + ty * 4 + i;
#pragma unroll
        for (int j = 0; j < 4; j++) {
            int o = o0 + tx * 4 + j;
            out[(size_t)r * CH + o] = acc[i][j] + bp[o];
        }
    }
}

// ============================================================
extern "C" void kernel_launch(void* const* d_in, const int* in_sizes, int n_in,
                              void* d_out, int out_size)
{
    const float* q    = (const float*)d_in[0];
    const float* k    = (const float*)d_in[1];
    const float* v    = (const float*)d_in[2];
    const float* Wq   = (const float*)d_in[3];
    const float* bq   = (const float*)d_in[4];
    const float* Wk   = (const float*)d_in[5];
    const float* bk   = (const float*)d_in[6];
    const float* Wv   = (const float*)d_in[7];
    const float* bv   = (const float*)d_in[8];
    const float* relw = (const float*)d_in[9];
    const float* relb = (const float*)d_in[10];
    const float* relv = (const float*)d_in[11];
    const float* Wp   = (const float*)d_in[12];
    const float* bp   = (const float*)d_in[13];
    (void)in_sizes; (void)n_in;

    float* out  = (float*)d_out;
    float* attn = (out_size >= OUT_ELEMS + ATTN_ELEMS) ? (out + OUT_ELEMS) : nullptr;

    static bool s_init = false;
    if (!s_init) {
        cudaFuncSetAttribute(attn_kernel,
                             cudaFuncAttributeMaxDynamicSharedMemorySize, SM_BYTES);
        s_init = true;
    }

    float* p_dst;
    cudaGetSymbolAddress((void**)&p_dst, g_pb);
    if (attn) p_dst = attn;

    proj_kernel<<<dim3(25, 2, 6), 256>>>(q, k, v, Wq, bq, Wk, bk, Wv, bv);
    relgemm_kernel<<<dim3(25, NHD, NB), 256>>>(relw, relb);
    attn_kernel<<<dim3(HI / GQ, NHD, NB), 640, SM_BYTES>>>(relv, p_dst);
    outproj_kernel<<<dim3(4, 50), 256>>>(Wp, bp, out);
}